// round 1
// baseline (speedup 1.0000x reference)
#include <cuda_runtime.h>
#include <cstdint>

// Problem constants
#define DIM    10
#define WIDTH  80
#define LEN_TH 971   // 10 + 10*80 + 80 + 80 + 1

// Offsets within a point's theta vector
#define OFF_BETA 0
#define OFF_A    10
#define OFF_B    810
#define OFF_C    890
#define OFF_D    970

// One warp per point. 8 warps (256 threads) per block.
__global__ __launch_bounds__(256) void u5_kernel(
    const float* __restrict__ theta,
    const float* __restrict__ x,
    float* __restrict__ out,
    int n_points)
{
    const int warp_in_block = threadIdx.x >> 5;
    const int lane = threadIdx.x & 31;
    const int p = blockIdx.x * 8 + warp_in_block;
    if (p >= n_points) return;

    const float* __restrict__ th = theta + (size_t)p * LEN_TH;
    const float* __restrict__ xp = x + (size_t)p * DIM;

    // u0[d] = sin(pi * (x[d] - beta[d])), lanes 0..9 compute, broadcast
    float my_u0 = 0.0f;
    if (lane < DIM) {
        my_u0 = sinpif(xp[lane] - th[OFF_BETA + lane]);
    }

    float u0[DIM];
#pragma unroll
    for (int d = 0; d < DIM; ++d) {
        u0[d] = __shfl_sync(0xffffffffu, my_u0, d);
    }

    // Each lane accumulates width columns: lane, lane+32, and (lane<16) lane+64
    float acc0 = 0.0f, acc1 = 0.0f, acc2 = 0.0f;
    const float* __restrict__ A = th + OFF_A;
#pragma unroll
    for (int d = 0; d < DIM; ++d) {
        const float* __restrict__ row = A + d * WIDTH;
        acc0 = fmaf(u0[d], __ldg(row + lane), acc0);
        acc1 = fmaf(u0[d], __ldg(row + lane + 32), acc1);
        if (lane < 16)
            acc2 = fmaf(u0[d], __ldg(row + lane + 64), acc2);
    }

    const float* __restrict__ B = th + OFF_B;
    const float* __restrict__ C = th + OFF_C;

    float h0 = tanhf(acc0 - __ldg(B + lane));
    float h1 = tanhf(acc1 - __ldg(B + lane + 32));
    float s  = h0 * __ldg(C + lane) + h1 * __ldg(C + lane + 32);
    if (lane < 16) {
        float h2 = tanhf(acc2 - __ldg(B + lane + 64));
        s = fmaf(h2, __ldg(C + lane + 64), s);
    }

    // Warp reduction
#pragma unroll
    for (int off = 16; off > 0; off >>= 1)
        s += __shfl_xor_sync(0xffffffffu, s, off);

    if (lane == 0)
        out[p] = s - th[OFF_D];
}

extern "C" void kernel_launch(void* const* d_in, const int* in_sizes, int n_in,
                              void* d_out, int out_size)
{
    const float* theta = (const float*)d_in[0];
    const float* x     = (const float*)d_in[1];
    float* out = (float*)d_out;

    const int n_points = out_size;            // 256*1024 = 262144
    const int warps_per_block = 8;            // 256 threads
    const int blocks = (n_points + warps_per_block - 1) / warps_per_block;

    u5_kernel<<<blocks, 256>>>(theta, x, out, n_points);
}